// round 12
// baseline (speedup 1.0000x reference)
#include <cuda_runtime.h>
#include <cuda_bf16.h>
#include <cuda_fp16.h>

#define NCI 16
#define NCO 32
#define NBR 3
#define NTERM (NCI * 9 * NBR)   // 432 per co
#define HH 32
#define WW 32
#define NBATCH 4

__device__ __forceinline__ __half2 tanh2_approx(__half2 x) {
    unsigned xi = *(unsigned*)&x;
    unsigned yi;
    asm("tanh.approx.f16x2 %0, %1;" : "=r"(yi) : "r"(xi));
    return *(__half2*)&yi;
}

// Odd deg-13 poly tanh on clamp(y,±2.6) PLUS linear tail segment on [2.6, 3.2]
// (odd by construction: clamp(y,±3.2)-clamp(y,±2.6)), constant beyond 3.2.
// Tail residual beyond 3.2 is suppressed by downstream sensitivity.
__device__ __forceinline__ __half2 tanh2_poly(__half2 y) {
    const __half2 M26 = __float2half2_rn(-2.599609375f);
    const __half2 P26 = __float2half2_rn( 2.599609375f);
    const __half2 M32 = __float2half2_rn(-3.19921875f);
    const __half2 P32 = __float2half2_rn( 3.19921875f);
    const __half2 S1  = __float2half2_rn( 0.0121966f);   // (tanh(3.2)-poly(2.6))/0.6
    const __half2 E13 = __float2half2_rn( 4.4322e-6f);
    const __half2 E11 = __float2half2_rn(-1.56882e-4f);
    const __half2 E9  = __float2half2_rn( 2.3000e-3f);
    const __half2 E7  = __float2half2_rn(-1.83644e-2f);
    const __half2 E5  = __float2half2_rn( 9.01123e-2f);
    const __half2 E3  = __float2half2_rn(-3.061580e-1f);
    const __half2 E1  = __float2half2_rn( 9.939351e-1f);
    __half2 yc  = __hmin2(__hmax2(y, M26), P26);
    __half2 c32 = __hmin2(__hmax2(y, M32), P32);
    __half2 z   = __hmul2(yc, yc);
    __half2 p   = __hfma2(z, E13, E11);
    p = __hfma2(p, z, E9);
    p = __hfma2(p, z, E7);
    p = __hfma2(p, z, E5);
    p = __hfma2(p, z, E3);
    p = __hfma2(p, z, E1);
    // t = yc*p + S1*(c32 - yc)
    return __hfma2(S1, __hsub2(c32, yc), __hmul2(yc, p));
}

// Block = (b, co, 4-row tile). 192 threads = 2 pair-groups x 3 nb x 32 cols.
// Each thread: one vertical pixel pair (half2), one nb branch, all 16 ci.
// Inner tanh: FMA-pipe poly everywhere; outer tanh: MUFU f16x2.
__global__ __launch_bounds__(192, 7)
void ferro_main_kernel(const float* __restrict__ x,
                       const float* __restrict__ k,
                       const float* __restrict__ Ec,
                       const float* __restrict__ Ps,
                       const float* __restrict__ bias,
                       const float* __restrict__ coef,
                       const float* __restrict__ out_bias,
                       float* __restrict__ out) {
    __shared__ uint4   sA[NTERM];         // {h2(5Ec), h2(k), h2(0.9kEc), h2(0.1kEc)}
    __shared__ float   sC[NTERM];         // coef*Ps (f32)
    __shared__ __half2 sxp[NCI][5][34];   // sliding vertical-pair rows, padded cols
    __shared__ float   sP[2][2][32][2];   // partials from nb-groups 1,2: [nb-1][pg][wo][px]
    __shared__ float   sRed[6];

    int tid  = threadIdx.x;
    int tile = blockIdx.x & 7;            // 8 tiles of 4 output rows
    int co   = (blockIdx.x >> 3) & 31;
    int b    = blockIdx.x >> 8;
    int r0   = tile * 4;

    // ---- stage x tile as vertical-pair half2: 16 ci x 5 rr x 8 col-groups = 640
    for (int idx = tid; idx < 640; idx += 192) {
        int c4  = idx & 7;
        int rr  = (idx >> 3) % 5;
        int ci  = idx / 40;
        int g0  = r0 - 1 + rr;            // low-half tap row
        int g1  = r0 + rr;                // high-half tap row
        const float* base = x + ((b * NCI + ci) * HH) * WW + c4 * 4;
        float4 v0 = make_float4(0.f, 0.f, 0.f, 0.f);
        float4 v1 = make_float4(0.f, 0.f, 0.f, 0.f);
        if ((unsigned)g0 < 32u) v0 = *(const float4*)(base + g0 * WW);
        if ((unsigned)g1 < 32u) v1 = *(const float4*)(base + g1 * WW);
        int cb0 = c4 * 4 + 1;
        sxp[ci][rr][cb0 + 0] = __floats2half2_rn(v0.x, v1.x);
        sxp[ci][rr][cb0 + 1] = __floats2half2_rn(v0.y, v1.y);
        sxp[ci][rr][cb0 + 2] = __floats2half2_rn(v0.z, v1.z);
        sxp[ci][rr][cb0 + 3] = __floats2half2_rn(v0.w, v1.w);
    }
    if (tid < 80) {                       // zero pad columns: 16 ci x 5 rr
        int ci = tid / 5, rr = tid % 5;
        sxp[ci][rr][0]  = __float2half2_rn(0.f);
        sxp[ci][rr][33] = __float2half2_rn(0.f);
    }

    // ---- pack params for this co (432 terms = 108 float4 groups)
    float cb = 0.0f;
    if (tid < NTERM / 4) {
        const float4* k4 = (const float4*)(k    + co * NTERM);
        const float4* e4 = (const float4*)(Ec   + co * NTERM);
        const float4* p4 = (const float4*)(Ps   + co * NTERM);
        const float4* b4 = (const float4*)(bias + co * NTERM);
        const float4* c4 = (const float4*)(coef + co * NTERM);
        float4 kk = k4[tid], ee = e4[tid], pp = p4[tid], bb = b4[tid], cc = c4[tid];
        float kkv[4] = {kk.x, kk.y, kk.z, kk.w};
        float eev[4] = {ee.x, ee.y, ee.z, ee.w};
        float ppv[4] = {pp.x, pp.y, pp.z, pp.w};
        float bbv[4] = {bb.x, bb.y, bb.z, bb.w};
        float ccv[4] = {cc.x, cc.y, cc.z, cc.w};
        #pragma unroll
        for (int j = 0; j < 4; j++) {
            float ke = kkv[j] * eev[j];
            __half2 e5 = __float2half2_rn(5.0f * eev[j]);
            __half2 kh = __float2half2_rn(kkv[j]);
            __half2 z9 = __float2half2_rn(0.9f * ke);
            __half2 w1 = __float2half2_rn(0.1f * ke);
            uint4 u;
            u.x = *(unsigned*)&e5;
            u.y = *(unsigned*)&kh;
            u.z = *(unsigned*)&z9;
            u.w = *(unsigned*)&w1;
            sA[tid * 4 + j] = u;
            sC[tid * 4 + j] = ccv[j] * ppv[j];
            cb += ccv[j] * bbv[j];
        }
    }
    // block-reduce cb (position-independent term) over 6 warps
    #pragma unroll
    for (int s = 16; s > 0; s >>= 1)
        cb += __shfl_xor_sync(0xFFFFFFFFu, cb, s);
    if ((tid & 31) == 0) sRed[tid >> 5] = cb;
    __syncthreads();
    float bc = ((sRed[0] + sRed[1]) + (sRed[2] + sRed[3]))
             + ((sRed[4] + sRed[5]) + out_bias[co]);

    int pg = tid / 96;        // pair-group: 0 -> rows r0,r0+1; 1 -> r0+2,r0+3
    int r  = tid % 96;
    int nb = r >> 5;          // 0..2
    int wo = r & 31;          // output col

    const __half2 FIVE2 = __float2half2_rn(5.0f);

    float acc0 = 0.f, acc1 = 0.f;

    #pragma unroll 1
    for (int ci = 0; ci < NCI; ci++) {
        // 9 taps for this thread's pair (pg selects the sliding row offset)
        __half2 xh[9];
        #pragma unroll
        for (int dy = 0; dy < 3; dy++)
            #pragma unroll
            for (int dx = 0; dx < 3; dx++)
                xh[dy * 3 + dx] = sxp[ci][2 * pg + dy][wo + dx];

        const uint4* pa = &sA[ci * 27 + nb * 9];
        const float* pc = &sC[ci * 27 + nb * 9];
        #pragma unroll
        for (int q = 0; q < 9; q++) {
            uint4 u  = pa[q];
            float cp = pc[q];
            __half2 e5 = *(__half2*)&u.x;
            __half2 kh = *(__half2*)&u.y;
            __half2 z9 = *(__half2*)&u.z;
            __half2 w1 = *(__half2*)&u.w;
            __half2 xp = xh[q];
            __half2 y  = __hfma2(xp, FIVE2, e5);   // 5x + 5Ec
            __half2 g  = __hfma2(xp, kh, z9);      // kx + 0.9kEc
            __half2 t1 = tanh2_poly(y);            // FMA/ALU pipes only
            __half2 t2 = tanh2_approx(__hfma2(t1, w1, g));
            acc0 = fmaf(cp, __low2float(t2),  acc0);
            acc1 = fmaf(cp, __high2float(t2), acc1);
        }
    }

    if (nb > 0) {
        sP[nb - 1][pg][wo][0] = acc0;
        sP[nb - 1][pg][wo][1] = acc1;
    }
    __syncthreads();
    if (nb == 0) {
        int ho = r0 + 2 * pg;
        float* op = out + (((b * NCO + co) * HH + ho) * WW) + wo;
        op[0]  = ((acc0 + sP[0][pg][wo][0]) + (sP[1][pg][wo][0] + bc));
        op[WW] = ((acc1 + sP[0][pg][wo][1]) + (sP[1][pg][wo][1] + bc));
    }
}

extern "C" void kernel_launch(void* const* d_in, const int* in_sizes, int n_in,
                              void* d_out, int out_size) {
    const float* x        = (const float*)d_in[0];
    const float* k        = (const float*)d_in[1];
    const float* Ec       = (const float*)d_in[2];
    const float* Ps       = (const float*)d_in[3];
    const float* bias     = (const float*)d_in[4];
    const float* coef     = (const float*)d_in[5];
    const float* out_bias = (const float*)d_in[6];
    float* out = (float*)d_out;

    ferro_main_kernel<<<NBATCH * NCO * 8, 192>>>(x, k, Ec, Ps, bias, coef, out_bias, out);
}

// round 13
// speedup vs baseline: 1.0543x; 1.0543x over previous
#include <cuda_runtime.h>
#include <cuda_bf16.h>
#include <cuda_fp16.h>

#define NCI 16
#define NCO 32
#define NBR 3
#define NTERM (NCI * 9 * NBR)   // 432 per co
#define HH 32
#define WW 32
#define NBATCH 4

__device__ __forceinline__ __half2 tanh2_approx(__half2 x) {
    unsigned xi = *(unsigned*)&x;
    unsigned yi;
    asm("tanh.approx.f16x2 %0, %1;" : "=r"(yi) : "r"(xi));
    return *(__half2*)&yi;
}

// Odd deg-13 poly tanh on clamp(y,±2.6) PLUS linear tail segment on [2.6, 3.2]
// (odd by construction: clamp(y,±3.2)-clamp(y,±2.6)), constant beyond 3.2.
// Residual beyond 3.2 is suppressed by downstream sensitivity (0.1kEc*(1-t2^2)).
__device__ __forceinline__ __half2 tanh2_poly(__half2 y) {
    const __half2 M26 = __float2half2_rn(-2.599609375f);
    const __half2 P26 = __float2half2_rn( 2.599609375f);
    const __half2 M32 = __float2half2_rn(-3.19921875f);
    const __half2 P32 = __float2half2_rn( 3.19921875f);
    const __half2 S1  = __float2half2_rn( 0.0121966f);   // (tanh(3.2)-poly(2.6))/0.6
    const __half2 E13 = __float2half2_rn( 4.4322e-6f);
    const __half2 E11 = __float2half2_rn(-1.56882e-4f);
    const __half2 E9  = __float2half2_rn( 2.3000e-3f);
    const __half2 E7  = __float2half2_rn(-1.83644e-2f);
    const __half2 E5  = __float2half2_rn( 9.01123e-2f);
    const __half2 E3  = __float2half2_rn(-3.061580e-1f);
    const __half2 E1  = __float2half2_rn( 9.939351e-1f);
    __half2 yc  = __hmin2(__hmax2(y, M26), P26);
    __half2 c32 = __hmin2(__hmax2(y, M32), P32);
    __half2 z   = __hmul2(yc, yc);
    __half2 p   = __hfma2(z, E13, E11);
    p = __hfma2(p, z, E9);
    p = __hfma2(p, z, E7);
    p = __hfma2(p, z, E5);
    p = __hfma2(p, z, E3);
    p = __hfma2(p, z, E1);
    return __hfma2(S1, __hsub2(c32, yc), __hmul2(yc, p));
}

// Block = (b, co, 4-row tile). 128 threads = 4 ci-groups x 32 cols.
// Each thread: ALL 4 pixels of its tile column (2 vertical half2 pairs),
// 4 of 16 input channels. One param LDS feeds both pairs.
// Inner tanh: FMA-pipe poly everywhere; outer tanh: MUFU f16x2.
__global__ __launch_bounds__(128, 7)
void ferro_main_kernel(const float* __restrict__ x,
                       const float* __restrict__ k,
                       const float* __restrict__ Ec,
                       const float* __restrict__ Ps,
                       const float* __restrict__ bias,
                       const float* __restrict__ coef,
                       const float* __restrict__ out_bias,
                       float* __restrict__ out) {
    __shared__ uint4   sA[NTERM];         // {h2(5Ec), h2(k), h2(0.9kEc), h2(0.1kEc)}
    __shared__ float   sC[NTERM];         // coef*Ps (f32)
    __shared__ __half2 sxp[NCI][5][34];   // sliding vertical-pair rows, padded cols
    __shared__ float   sP[3][32][4];      // partials from ci-groups 1..3
    __shared__ float   sRed[4];

    int tid  = threadIdx.x;
    int tile = blockIdx.x & 7;            // 8 tiles of 4 output rows
    int co   = (blockIdx.x >> 3) & 31;
    int b    = blockIdx.x >> 8;
    int r0   = tile * 4;

    // ---- stage x tile as vertical-pair half2: 16 ci x 5 rr x 8 col-groups = 640
    #pragma unroll
    for (int i = 0; i < 5; i++) {
        int idx = tid + i * 128;
        int c4  = idx & 7;
        int rr  = (idx >> 3) % 5;
        int ci  = idx / 40;
        int g0  = r0 - 1 + rr;            // low-half tap row
        int g1  = r0 + rr;                // high-half tap row
        const float* base = x + ((b * NCI + ci) * HH) * WW + c4 * 4;
        float4 v0 = make_float4(0.f, 0.f, 0.f, 0.f);
        float4 v1 = make_float4(0.f, 0.f, 0.f, 0.f);
        if ((unsigned)g0 < 32u) v0 = *(const float4*)(base + g0 * WW);
        if ((unsigned)g1 < 32u) v1 = *(const float4*)(base + g1 * WW);
        int cb0 = c4 * 4 + 1;
        sxp[ci][rr][cb0 + 0] = __floats2half2_rn(v0.x, v1.x);
        sxp[ci][rr][cb0 + 1] = __floats2half2_rn(v0.y, v1.y);
        sxp[ci][rr][cb0 + 2] = __floats2half2_rn(v0.z, v1.z);
        sxp[ci][rr][cb0 + 3] = __floats2half2_rn(v0.w, v1.w);
    }
    if (tid < 80) {                       // zero pad columns: 16 ci x 5 rr
        int ci = tid / 5, rr = tid % 5;
        sxp[ci][rr][0]  = __float2half2_rn(0.f);
        sxp[ci][rr][33] = __float2half2_rn(0.f);
    }

    // ---- pack params for this co (432 terms = 108 float4 groups)
    float cb = 0.0f;
    if (tid < NTERM / 4) {
        const float4* k4 = (const float4*)(k    + co * NTERM);
        const float4* e4 = (const float4*)(Ec   + co * NTERM);
        const float4* p4 = (const float4*)(Ps   + co * NTERM);
        const float4* b4 = (const float4*)(bias + co * NTERM);
        const float4* c4 = (const float4*)(coef + co * NTERM);
        float4 kk = k4[tid], ee = e4[tid], pp = p4[tid], bb = b4[tid], cc = c4[tid];
        float kkv[4] = {kk.x, kk.y, kk.z, kk.w};
        float eev[4] = {ee.x, ee.y, ee.z, ee.w};
        float ppv[4] = {pp.x, pp.y, pp.z, pp.w};
        float bbv[4] = {bb.x, bb.y, bb.z, bb.w};
        float ccv[4] = {cc.x, cc.y, cc.z, cc.w};
        #pragma unroll
        for (int j = 0; j < 4; j++) {
            float ke = kkv[j] * eev[j];
            __half2 e5 = __float2half2_rn(5.0f * eev[j]);
            __half2 kh = __float2half2_rn(kkv[j]);
            __half2 z9 = __float2half2_rn(0.9f * ke);
            __half2 w1 = __float2half2_rn(0.1f * ke);
            uint4 u;
            u.x = *(unsigned*)&e5;
            u.y = *(unsigned*)&kh;
            u.z = *(unsigned*)&z9;
            u.w = *(unsigned*)&w1;
            sA[tid * 4 + j] = u;
            sC[tid * 4 + j] = ccv[j] * ppv[j];
            cb += ccv[j] * bbv[j];
        }
    }
    // block-reduce cb (position-independent term)
    #pragma unroll
    for (int s = 16; s > 0; s >>= 1)
        cb += __shfl_xor_sync(0xFFFFFFFFu, cb, s);
    if ((tid & 31) == 0) sRed[tid >> 5] = cb;
    __syncthreads();
    float bc = (sRed[0] + sRed[1]) + (sRed[2] + sRed[3]) + out_bias[co];

    int cig = tid >> 5;       // ci-group: 0..3 (4 channels each)
    int wo  = tid & 31;       // output col

    const __half2 FIVE2 = __float2half2_rn(5.0f);

    float acc0 = 0.f, acc1 = 0.f, acc2 = 0.f, acc3 = 0.f;

    #pragma unroll 1
    for (int c4i = 0; c4i < 4; c4i++) {
        int ci = cig * 4 + c4i;
        // 5 sliding row-pairs x 3 cols cover all taps of all 4 pixels:
        //  pair A (pixels r0, r0+1):   xh[dy*3+dx]
        //  pair B (pixels r0+2, r0+3): xh[(dy+2)*3+dx]
        __half2 xh[15];
        #pragma unroll
        for (int rr = 0; rr < 5; rr++)
            #pragma unroll
            for (int dx = 0; dx < 3; dx++)
                xh[rr * 3 + dx] = sxp[ci][rr][wo + dx];

        const uint4* pa = &sA[ci * 27];
        const float* pc = &sC[ci * 27];
        #pragma unroll
        for (int q = 0; q < 27; q++) {    // q = nb*9 + dy*3 + dx
            uint4 u  = pa[q];
            float cp = pc[q];
            __half2 e5 = *(__half2*)&u.x;
            __half2 kh = *(__half2*)&u.y;
            __half2 z9 = *(__half2*)&u.z;
            __half2 w1 = *(__half2*)&u.w;
            int ij = q % 9;
            int dy = ij / 3, dxx = ij % 3;
            __half2 xA = xh[dy * 3 + dxx];
            __half2 xB = xh[(dy + 2) * 3 + dxx];
            __half2 yA = __hfma2(xA, FIVE2, e5);
            __half2 yB = __hfma2(xB, FIVE2, e5);
            __half2 gA = __hfma2(xA, kh, z9);
            __half2 gB = __hfma2(xB, kh, z9);
            __half2 t1A = tanh2_poly(yA);         // FMA pipe only
            __half2 t1B = tanh2_poly(yB);
            __half2 t2A = tanh2_approx(__hfma2(t1A, w1, gA));   // MUFU
            __half2 t2B = tanh2_approx(__hfma2(t1B, w1, gB));
            acc0 = fmaf(cp, __low2float(t2A),  acc0);
            acc1 = fmaf(cp, __high2float(t2A), acc1);
            acc2 = fmaf(cp, __low2float(t2B),  acc2);
            acc3 = fmaf(cp, __high2float(t2B), acc3);
        }
    }

    if (cig > 0) {
        sP[cig - 1][wo][0] = acc0;
        sP[cig - 1][wo][1] = acc1;
        sP[cig - 1][wo][2] = acc2;
        sP[cig - 1][wo][3] = acc3;
    }
    __syncthreads();
    if (cig == 0) {
        float r[4] = {acc0, acc1, acc2, acc3};
        #pragma unroll
        for (int j = 0; j < 4; j++) {
            float v = ((r[j] + sP[0][wo][j]) + (sP[1][wo][j] + sP[2][wo][j])) + bc;
            out[(((b * NCO + co) * HH + (r0 + j)) * WW) + wo] = v;
        }
    }
}

extern "C" void kernel_launch(void* const* d_in, const int* in_sizes, int n_in,
                              void* d_out, int out_size) {
    const float* x        = (const float*)d_in[0];
    const float* k        = (const float*)d_in[1];
    const float* Ec       = (const float*)d_in[2];
    const float* Ps       = (const float*)d_in[3];
    const float* bias     = (const float*)d_in[4];
    const float* coef     = (const float*)d_in[5];
    const float* out_bias = (const float*)d_in[6];
    float* out = (float*)d_out;

    ferro_main_kernel<<<NBATCH * NCO * 8, 128>>>(x, k, Ec, Ps, bias, coef, out_bias, out);
}

// round 14
// speedup vs baseline: 1.1883x; 1.1272x over previous
#include <cuda_runtime.h>
#include <cuda_bf16.h>
#include <cuda_fp16.h>

#define NCI 16
#define NCO 32
#define NBR 3
#define NTERM (NCI * 9 * NBR)   // 432 per co
#define HH 32
#define WW 32
#define NBATCH 4

__device__ __forceinline__ __half2 tanh2_approx(__half2 x) {
    unsigned xi = *(unsigned*)&x;
    unsigned yi;
    asm("tanh.approx.f16x2 %0, %1;" : "=r"(yi) : "r"(xi));
    return *(__half2*)&yi;
}

// Odd deg-13 poly tanh on clamp(y,±2.6) PLUS linear tail segment on [2.6, 3.2]
// (odd by construction: clamp(y,±3.2)-clamp(y,±2.6)), constant beyond 3.2.
// Residual beyond 3.2 is suppressed by downstream sensitivity (0.1kEc*(1-t2^2)).
// Validated in R12/R13: full-poly rel_err 7.57e-4.
__device__ __forceinline__ __half2 tanh2_poly(__half2 y) {
    const __half2 M26 = __float2half2_rn(-2.599609375f);
    const __half2 P26 = __float2half2_rn( 2.599609375f);
    const __half2 M32 = __float2half2_rn(-3.19921875f);
    const __half2 P32 = __float2half2_rn( 3.19921875f);
    const __half2 S1  = __float2half2_rn( 0.0121966f);   // (tanh(3.2)-poly(2.6))/0.6
    const __half2 E13 = __float2half2_rn( 4.4322e-6f);
    const __half2 E11 = __float2half2_rn(-1.56882e-4f);
    const __half2 E9  = __float2half2_rn( 2.3000e-3f);
    const __half2 E7  = __float2half2_rn(-1.83644e-2f);
    const __half2 E5  = __float2half2_rn( 9.01123e-2f);
    const __half2 E3  = __float2half2_rn(-3.061580e-1f);
    const __half2 E1  = __float2half2_rn( 9.939351e-1f);
    __half2 yc  = __hmin2(__hmax2(y, M26), P26);
    __half2 c32 = __hmin2(__hmax2(y, M32), P32);
    __half2 z   = __hmul2(yc, yc);
    __half2 p   = __hfma2(z, E13, E11);
    p = __hfma2(p, z, E9);
    p = __hfma2(p, z, E7);
    p = __hfma2(p, z, E5);
    p = __hfma2(p, z, E3);
    p = __hfma2(p, z, E1);
    return __hfma2(S1, __hsub2(c32, yc), __hmul2(yc, p));
}

// Block = (b, co, 4-row tile). 128 threads = 4 ci-groups x 32 cols.
// Each thread: ALL 4 pixels of its tile column (2 vertical half2 pairs),
// 4 of 16 input channels. One param LDS feeds both pairs.
// Inner tanh: poly (FMA pipe) for nb 0,1 (f=2/3, the measured pipe-balance
// optimum); MUFU for nb 2. Outer tanh: MUFU f16x2 always.
__global__ __launch_bounds__(128, 7)
void ferro_main_kernel(const float* __restrict__ x,
                       const float* __restrict__ k,
                       const float* __restrict__ Ec,
                       const float* __restrict__ Ps,
                       const float* __restrict__ bias,
                       const float* __restrict__ coef,
                       const float* __restrict__ out_bias,
                       float* __restrict__ out) {
    __shared__ uint4   sA[NTERM];         // {h2(5Ec), h2(k), h2(0.9kEc), h2(0.1kEc)}
    __shared__ float   sC[NTERM];         // coef*Ps (f32)
    __shared__ __half2 sxp[NCI][5][34];   // sliding vertical-pair rows, padded cols
    __shared__ float   sP[3][32][4];      // partials from ci-groups 1..3
    __shared__ float   sRed[4];

    int tid  = threadIdx.x;
    int tile = blockIdx.x & 7;            // 8 tiles of 4 output rows
    int co   = (blockIdx.x >> 3) & 31;
    int b    = blockIdx.x >> 8;
    int r0   = tile * 4;

    // ---- stage x tile as vertical-pair half2: 16 ci x 5 rr x 8 col-groups = 640
    #pragma unroll
    for (int i = 0; i < 5; i++) {
        int idx = tid + i * 128;
        int c4  = idx & 7;
        int rr  = (idx >> 3) % 5;
        int ci  = idx / 40;
        int g0  = r0 - 1 + rr;            // low-half tap row
        int g1  = r0 + rr;                // high-half tap row
        const float* base = x + ((b * NCI + ci) * HH) * WW + c4 * 4;
        float4 v0 = make_float4(0.f, 0.f, 0.f, 0.f);
        float4 v1 = make_float4(0.f, 0.f, 0.f, 0.f);
        if ((unsigned)g0 < 32u) v0 = *(const float4*)(base + g0 * WW);
        if ((unsigned)g1 < 32u) v1 = *(const float4*)(base + g1 * WW);
        int cb0 = c4 * 4 + 1;
        sxp[ci][rr][cb0 + 0] = __floats2half2_rn(v0.x, v1.x);
        sxp[ci][rr][cb0 + 1] = __floats2half2_rn(v0.y, v1.y);
        sxp[ci][rr][cb0 + 2] = __floats2half2_rn(v0.z, v1.z);
        sxp[ci][rr][cb0 + 3] = __floats2half2_rn(v0.w, v1.w);
    }
    if (tid < 80) {                       // zero pad columns: 16 ci x 5 rr
        int ci = tid / 5, rr = tid % 5;
        sxp[ci][rr][0]  = __float2half2_rn(0.f);
        sxp[ci][rr][33] = __float2half2_rn(0.f);
    }

    // ---- pack params for this co (432 terms = 108 float4 groups)
    float cb = 0.0f;
    if (tid < NTERM / 4) {
        const float4* k4 = (const float4*)(k    + co * NTERM);
        const float4* e4 = (const float4*)(Ec   + co * NTERM);
        const float4* p4 = (const float4*)(Ps   + co * NTERM);
        const float4* b4 = (const float4*)(bias + co * NTERM);
        const float4* c4 = (const float4*)(coef + co * NTERM);
        float4 kk = k4[tid], ee = e4[tid], pp = p4[tid], bb = b4[tid], cc = c4[tid];
        float kkv[4] = {kk.x, kk.y, kk.z, kk.w};
        float eev[4] = {ee.x, ee.y, ee.z, ee.w};
        float ppv[4] = {pp.x, pp.y, pp.z, pp.w};
        float bbv[4] = {bb.x, bb.y, bb.z, bb.w};
        float ccv[4] = {cc.x, cc.y, cc.z, cc.w};
        #pragma unroll
        for (int j = 0; j < 4; j++) {
            float ke = kkv[j] * eev[j];
            __half2 e5 = __float2half2_rn(5.0f * eev[j]);
            __half2 kh = __float2half2_rn(kkv[j]);
            __half2 z9 = __float2half2_rn(0.9f * ke);
            __half2 w1 = __float2half2_rn(0.1f * ke);
            uint4 u;
            u.x = *(unsigned*)&e5;
            u.y = *(unsigned*)&kh;
            u.z = *(unsigned*)&z9;
            u.w = *(unsigned*)&w1;
            sA[tid * 4 + j] = u;
            sC[tid * 4 + j] = ccv[j] * ppv[j];
            cb += ccv[j] * bbv[j];
        }
    }
    // block-reduce cb (position-independent term)
    #pragma unroll
    for (int s = 16; s > 0; s >>= 1)
        cb += __shfl_xor_sync(0xFFFFFFFFu, cb, s);
    if ((tid & 31) == 0) sRed[tid >> 5] = cb;
    __syncthreads();
    float bc = (sRed[0] + sRed[1]) + (sRed[2] + sRed[3]) + out_bias[co];

    int cig = tid >> 5;       // ci-group: 0..3 (4 channels each)
    int wo  = tid & 31;       // output col

    const __half2 FIVE2 = __float2half2_rn(5.0f);

    float acc0 = 0.f, acc1 = 0.f, acc2 = 0.f, acc3 = 0.f;

    #pragma unroll 1
    for (int c4i = 0; c4i < 4; c4i++) {
        int ci = cig * 4 + c4i;
        // 5 sliding row-pairs x 3 cols cover all taps of all 4 pixels:
        //  pair A (pixels r0, r0+1):   xh[dy*3+dx]
        //  pair B (pixels r0+2, r0+3): xh[(dy+2)*3+dx]
        __half2 xh[15];
        #pragma unroll
        for (int rr = 0; rr < 5; rr++)
            #pragma unroll
            for (int dx = 0; dx < 3; dx++)
                xh[rr * 3 + dx] = sxp[ci][rr][wo + dx];

        const uint4* pa = &sA[ci * 27];
        const float* pc = &sC[ci * 27];
        #pragma unroll
        for (int q = 0; q < 27; q++) {    // q = nb*9 + dy*3 + dx
            uint4 u  = pa[q];
            float cp = pc[q];
            __half2 e5 = *(__half2*)&u.x;
            __half2 kh = *(__half2*)&u.y;
            __half2 z9 = *(__half2*)&u.z;
            __half2 w1 = *(__half2*)&u.w;
            int ij = q % 9;
            int dy = ij / 3, dxx = ij % 3;
            __half2 xA = xh[dy * 3 + dxx];
            __half2 xB = xh[(dy + 2) * 3 + dxx];
            __half2 yA = __hfma2(xA, FIVE2, e5);
            __half2 yB = __hfma2(xB, FIVE2, e5);
            __half2 gA = __hfma2(xA, kh, z9);
            __half2 gB = __hfma2(xB, kh, z9);
            __half2 t1A, t1B;
            if (q < 18) {                 // nb 0,1: FMA-pipe polynomial
                t1A = tanh2_poly(yA);
                t1B = tanh2_poly(yB);
            } else {                      // nb 2: MUFU
                t1A = tanh2_approx(yA);
                t1B = tanh2_approx(yB);
            }
            __half2 t2A = tanh2_approx(__hfma2(t1A, w1, gA));
            __half2 t2B = tanh2_approx(__hfma2(t1B, w1, gB));
            acc0 = fmaf(cp, __low2float(t2A),  acc0);
            acc1 = fmaf(cp, __high2float(t2A), acc1);
            acc2 = fmaf(cp, __low2float(t2B),  acc2);
            acc3 = fmaf(cp, __high2float(t2B), acc3);
        }
    }

    if (cig > 0) {
        sP[cig - 1][wo][0] = acc0;
        sP[cig - 1][wo][1] = acc1;
        sP[cig - 1][wo][2] = acc2;
        sP[cig - 1][wo][3] = acc3;
    }
    __syncthreads();
    if (cig == 0) {
        float r[4] = {acc0, acc1, acc2, acc3};
        #pragma unroll
        for (int j = 0; j < 4; j++) {
            float v = ((r[j] + sP[0][wo][j]) + (sP[1][wo][j] + sP[2][wo][j])) + bc;
            out[(((b * NCO + co) * HH + (r0 + j)) * WW) + wo] = v;
        }
    }
}

extern "C" void kernel_launch(void* const* d_in, const int* in_sizes, int n_in,
                              void* d_out, int out_size) {
    const float* x        = (const float*)d_in[0];
    const float* k        = (const float*)d_in[1];
    const float* Ec       = (const float*)d_in[2];
    const float* Ps       = (const float*)d_in[3];
    const float* bias     = (const float*)d_in[4];
    const float* coef     = (const float*)d_in[5];
    const float* out_bias = (const float*)d_in[6];
    float* out = (float*)d_out;

    ferro_main_kernel<<<NBATCH * NCO * 8, 128>>>(x, k, Ec, Ps, bias, coef, out_bias, out);
}

// round 16
// speedup vs baseline: 1.2541x; 1.0553x over previous
#include <cuda_runtime.h>
#include <cuda_bf16.h>
#include <cuda_fp16.h>

#define NCI 16
#define NCO 32
#define NBR 3
#define NTERM (NCI * 9 * NBR)   // 432 per co
#define HH 32
#define WW 32
#define NBATCH 4

__device__ __forceinline__ __half2 tanh2_approx(__half2 x) {
    unsigned xi = *(unsigned*)&x;
    unsigned yi;
    asm("tanh.approx.f16x2 %0, %1;" : "=r"(yi) : "r"(xi));
    return *(__half2*)&yi;
}

// Odd deg-13 poly tanh on clamp(y,±2.6) + linear tail to 3.2, with the tail
// slope S1 FOLDED into the Horner constant term (E1' = E1 - S1):
//   t = yc*p' + S1*c32  ==  yc*p + S1*(c32 - yc)
__device__ __forceinline__ __half2 tanh2_poly(__half2 y) {
    const __half2 M26 = __float2half2_rn(-2.599609375f);
    const __half2 P26 = __float2half2_rn( 2.599609375f);
    const __half2 M32 = __float2half2_rn(-3.19921875f);
    const __half2 P32 = __float2half2_rn( 3.19921875f);
    const __half2 S1  = __float2half2_rn( 0.0121966f);
    const __half2 E13 = __float2half2_rn( 4.4322e-6f);
    const __half2 E11 = __float2half2_rn(-1.56882e-4f);
    const __half2 E9  = __float2half2_rn( 2.3000e-3f);
    const __half2 E7  = __float2half2_rn(-1.83644e-2f);
    const __half2 E5  = __float2half2_rn( 9.01123e-2f);
    const __half2 E3  = __float2half2_rn(-3.061580e-1f);
    const __half2 E1M = __float2half2_rn( 0.9817385f);   // E1 - S1
    __half2 yc  = __hmin2(__hmax2(y, M26), P26);
    __half2 c32 = __hmin2(__hmax2(y, M32), P32);
    __half2 z   = __hmul2(yc, yc);
    __half2 p   = __hfma2(z, E13, E11);
    p = __hfma2(p, z, E9);
    p = __hfma2(p, z, E7);
    p = __hfma2(p, z, E5);
    p = __hfma2(p, z, E3);
    p = __hfma2(p, z, E1M);
    return __hfma2(yc, p, __hmul2(S1, c32));
}

// Block = (b, co, 4-row tile). 128 threads = 4 ci-groups x 32 cols.
// Each thread: ALL 4 pixels of its tile column (2 vertical half2 pairs),
// 4 of 16 input channels. Inner tanh: poly (FMA pipe) for nb 0,1; MUFU nb 2.
// Accumulation: f16 half2 windows of 3 terms, flushed to f32.
__global__ __launch_bounds__(128, 7)
void ferro_main_kernel(const float* __restrict__ x,
                       const float* __restrict__ k,
                       const float* __restrict__ Ec,
                       const float* __restrict__ Ps,
                       const float* __restrict__ bias,
                       const float* __restrict__ coef,
                       const float* __restrict__ out_bias,
                       float* __restrict__ out) {
    __shared__ uint4   sA[NTERM];         // {h2(5Ec), h2(k), h2(0.9kEc), h2(0.1kEc)}
    __shared__ __half2 sC2[NTERM];        // {cp, cp} as half2
    __shared__ __half2 sxp[NCI][5][34];   // sliding vertical-pair rows, padded cols
    __shared__ float   sP[3][32][4];      // partials from ci-groups 1..3
    __shared__ float   sRed[4];

    int tid  = threadIdx.x;
    int tile = blockIdx.x & 7;            // 8 tiles of 4 output rows
    int co   = (blockIdx.x >> 3) & 31;
    int b    = blockIdx.x >> 8;
    int r0   = tile * 4;

    // ---- stage x tile as vertical-pair half2: 16 ci x 5 rr x 8 col-groups = 640
    #pragma unroll
    for (int i = 0; i < 5; i++) {
        int idx = tid + i * 128;
        int c4  = idx & 7;
        int rr  = (idx >> 3) % 5;
        int ci  = idx / 40;
        int g0  = r0 - 1 + rr;            // low-half tap row
        int g1  = r0 + rr;                // high-half tap row
        const float* base = x + ((b * NCI + ci) * HH) * WW + c4 * 4;
        float4 v0 = make_float4(0.f, 0.f, 0.f, 0.f);
        float4 v1 = make_float4(0.f, 0.f, 0.f, 0.f);
        if ((unsigned)g0 < 32u) v0 = *(const float4*)(base + g0 * WW);
        if ((unsigned)g1 < 32u) v1 = *(const float4*)(base + g1 * WW);
        int cb0 = c4 * 4 + 1;
        sxp[ci][rr][cb0 + 0] = __floats2half2_rn(v0.x, v1.x);
        sxp[ci][rr][cb0 + 1] = __floats2half2_rn(v0.y, v1.y);
        sxp[ci][rr][cb0 + 2] = __floats2half2_rn(v0.z, v1.z);
        sxp[ci][rr][cb0 + 3] = __floats2half2_rn(v0.w, v1.w);
    }
    if (tid < 80) {                       // zero pad columns: 16 ci x 5 rr
        int ci = tid / 5, rr = tid % 5;
        sxp[ci][rr][0]  = __float2half2_rn(0.f);
        sxp[ci][rr][33] = __float2half2_rn(0.f);
    }

    // ---- pack params for this co (432 terms = 108 float4 groups)
    float cb = 0.0f;
    if (tid < NTERM / 4) {
        const float4* k4 = (const float4*)(k    + co * NTERM);
        const float4* e4 = (const float4*)(Ec   + co * NTERM);
        const float4* p4 = (const float4*)(Ps   + co * NTERM);
        const float4* b4 = (const float4*)(bias + co * NTERM);
        const float4* c4 = (const float4*)(coef + co * NTERM);
        float4 kk = k4[tid], ee = e4[tid], pp = p4[tid], bb = b4[tid], cc = c4[tid];
        float kkv[4] = {kk.x, kk.y, kk.z, kk.w};
        float eev[4] = {ee.x, ee.y, ee.z, ee.w};
        float ppv[4] = {pp.x, pp.y, pp.z, pp.w};
        float bbv[4] = {bb.x, bb.y, bb.z, bb.w};
        float ccv[4] = {cc.x, cc.y, cc.z, cc.w};
        #pragma unroll
        for (int j = 0; j < 4; j++) {
            float ke = kkv[j] * eev[j];
            __half2 e5 = __float2half2_rn(5.0f * eev[j]);
            __half2 kh = __float2half2_rn(kkv[j]);
            __half2 z9 = __float2half2_rn(0.9f * ke);
            __half2 w1 = __float2half2_rn(0.1f * ke);
            uint4 u;
            u.x = *(unsigned*)&e5;
            u.y = *(unsigned*)&kh;
            u.z = *(unsigned*)&z9;
            u.w = *(unsigned*)&w1;
            sA[tid * 4 + j] = u;
            sC2[tid * 4 + j] = __float2half2_rn(ccv[j] * ppv[j]);
            cb += ccv[j] * bbv[j];
        }
    }
    // block-reduce cb (position-independent term)
    #pragma unroll
    for (int s = 16; s > 0; s >>= 1)
        cb += __shfl_xor_sync(0xFFFFFFFFu, cb, s);
    if ((tid & 31) == 0) sRed[tid >> 5] = cb;
    __syncthreads();
    float bc = (sRed[0] + sRed[1]) + (sRed[2] + sRed[3]) + out_bias[co];

    int cig = tid >> 5;       // ci-group: 0..3 (4 channels each)
    int wo  = tid & 31;       // output col

    const __half2 FIVE2 = __float2half2_rn(5.0f);
    const __half2 ZERO2 = __float2half2_rn(0.0f);

    float acc0 = 0.f, acc1 = 0.f, acc2 = 0.f, acc3 = 0.f;

    #pragma unroll 1
    for (int c4i = 0; c4i < 4; c4i++) {
        int ci = cig * 4 + c4i;
        // 5 sliding row-pairs x 3 cols cover all taps of all 4 pixels:
        //  pair A (pixels r0, r0+1):   xh[dy*3+dx]
        //  pair B (pixels r0+2, r0+3): xh[(dy+2)*3+dx]
        __half2 xh[15];
        #pragma unroll
        for (int rr = 0; rr < 5; rr++)
            #pragma unroll
            for (int dx = 0; dx < 3; dx++)
                xh[rr * 3 + dx] = sxp[ci][rr][wo + dx];

        const uint4*   pa = &sA[ci * 27];
        const __half2* pc = &sC2[ci * 27];
        #pragma unroll
        for (int q0 = 0; q0 < 27; q0 += 3) {  // windows of 3 terms (same nb)
            __half2 wA = ZERO2, wB = ZERO2;
            #pragma unroll
            for (int j = 0; j < 3; j++) {
                int q = q0 + j;               // q = nb*9 + dy*3 + dx
                uint4   u   = pa[q];
                __half2 cp2 = pc[q];
                __half2 e5 = *(__half2*)&u.x;
                __half2 kh = *(__half2*)&u.y;
                __half2 z9 = *(__half2*)&u.z;
                __half2 w1 = *(__half2*)&u.w;
                int ij = q % 9;
                int dy = ij / 3, dxx = ij % 3;
                __half2 xA = xh[dy * 3 + dxx];
                __half2 xB = xh[(dy + 2) * 3 + dxx];
                __half2 yA = __hfma2(xA, FIVE2, e5);
                __half2 yB = __hfma2(xB, FIVE2, e5);
                __half2 gA = __hfma2(xA, kh, z9);
                __half2 gB = __hfma2(xB, kh, z9);
                __half2 t1A, t1B;
                if (q < 18) {                 // nb 0,1: FMA-pipe polynomial
                    t1A = tanh2_poly(yA);
                    t1B = tanh2_poly(yB);
                } else {                      // nb 2: MUFU
                    t1A = tanh2_approx(yA);
                    t1B = tanh2_approx(yB);
                }
                __half2 t2A = tanh2_approx(__hfma2(t1A, w1, gA));
                __half2 t2B = tanh2_approx(__hfma2(t1B, w1, gB));
                wA = __hfma2(cp2, t2A, wA);   // f16 window accumulate
                wB = __hfma2(cp2, t2B, wB);
            }
            // flush window to f32 accumulators
            float2 fA = __half22float2(wA);
            float2 fB = __half22float2(wB);
            acc0 += fA.x;
            acc1 += fA.y;
            acc2 += fB.x;
            acc3 += fB.y;
        }
    }

    if (cig > 0) {
        sP[cig - 1][wo][0] = acc0;
        sP[cig - 1][wo][1] = acc1;
        sP[cig - 1][wo][2] = acc2;
        sP[cig - 1][wo][3] = acc3;
    }
    __syncthreads();
    if (cig == 0) {
        float r[4] = {acc0, acc1, acc2, acc3};
        #pragma unroll
        for (int j = 0; j < 4; j++) {
            float v = ((r[j] + sP[0][wo][j]) + (sP[1][wo][j] + sP[2][wo][j])) + bc;
            out[(((b * NCO + co) * HH + (r0 + j)) * WW) + wo] = v;
        }
    }
}

extern "C" void kernel_launch(void* const* d_in, const int* in_sizes, int n_in,
                              void* d_out, int out_size) {
    const float* x        = (const float*)d_in[0];
    const float* k        = (const float*)d_in[1];
    const float* Ec       = (const float*)d_in[2];
    const float* Ps       = (const float*)d_in[3];
    const float* bias     = (const float*)d_in[4];
    const float* coef     = (const float*)d_in[5];
    const float* out_bias = (const float*)d_in[6];
    float* out = (float*)d_out;

    ferro_main_kernel<<<NBATCH * NCO * 8, 128>>>(x, k, Ec, Ps, bias, coef, out_bias, out);
}

// round 17
// speedup vs baseline: 1.2710x; 1.0135x over previous
#include <cuda_runtime.h>
#include <cuda_bf16.h>
#include <cuda_fp16.h>

#define NCI 16
#define NCO 32
#define NBR 3
#define NTERM (NCI * 9 * NBR)   // 432 per co
#define HH 32
#define WW 32
#define NBATCH 4

__device__ __forceinline__ __half2 tanh2_approx(__half2 x) {
    unsigned xi = *(unsigned*)&x;
    unsigned yi;
    asm("tanh.approx.f16x2 %0, %1;" : "=r"(yi) : "r"(xi));
    return *(__half2*)&yi;
}

// Odd deg-13 poly tanh on clamp(y,±2.6) + linear tail to 3.2, with the tail
// slope S1 FOLDED into the Horner constant term (E1' = E1 - S1):
//   t = yc*p' + S1*c32  ==  yc*p + S1*(c32 - yc)
__device__ __forceinline__ __half2 tanh2_poly(__half2 y) {
    const __half2 M26 = __float2half2_rn(-2.599609375f);
    const __half2 P26 = __float2half2_rn( 2.599609375f);
    const __half2 M32 = __float2half2_rn(-3.19921875f);
    const __half2 P32 = __float2half2_rn( 3.19921875f);
    const __half2 S1  = __float2half2_rn( 0.0121966f);
    const __half2 E13 = __float2half2_rn( 4.4322e-6f);
    const __half2 E11 = __float2half2_rn(-1.56882e-4f);
    const __half2 E9  = __float2half2_rn( 2.3000e-3f);
    const __half2 E7  = __float2half2_rn(-1.83644e-2f);
    const __half2 E5  = __float2half2_rn( 9.01123e-2f);
    const __half2 E3  = __float2half2_rn(-3.061580e-1f);
    const __half2 E1M = __float2half2_rn( 0.9817385f);   // E1 - S1
    __half2 yc  = __hmin2(__hmax2(y, M26), P26);
    __half2 c32 = __hmin2(__hmax2(y, M32), P32);
    __half2 z   = __hmul2(yc, yc);
    __half2 p   = __hfma2(z, E13, E11);
    p = __hfma2(p, z, E9);
    p = __hfma2(p, z, E7);
    p = __hfma2(p, z, E5);
    p = __hfma2(p, z, E3);
    p = __hfma2(p, z, E1M);
    return __hfma2(yc, p, __hmul2(S1, c32));
}

// Block = (b, co, 4-row tile). 128 threads = 4 ci-groups x 32 cols.
// Each thread: ALL 4 pixels of its tile column (2 vertical half2 pairs),
// 4 of 16 input channels. Inner tanh: poly (FMA pipe) for q<11 (f=11/27,
// the issue/MUFU pipe-balance optimum of the measured 3-pipe model);
// MUFU otherwise. Accumulation: f16 half2 windows of 3 terms, flushed to f32.
__global__ __launch_bounds__(128, 7)
void ferro_main_kernel(const float* __restrict__ x,
                       const float* __restrict__ k,
                       const float* __restrict__ Ec,
                       const float* __restrict__ Ps,
                       const float* __restrict__ bias,
                       const float* __restrict__ coef,
                       const float* __restrict__ out_bias,
                       float* __restrict__ out) {
    __shared__ uint4   sA[NTERM];         // {h2(5Ec), h2(k), h2(0.9kEc), h2(0.1kEc)}
    __shared__ __half2 sC2[NTERM];        // {cp, cp} as half2
    __shared__ __half2 sxp[NCI][5][34];   // sliding vertical-pair rows, padded cols
    __shared__ float   sP[3][32][4];      // partials from ci-groups 1..3
    __shared__ float   sRed[4];

    int tid  = threadIdx.x;
    int tile = blockIdx.x & 7;            // 8 tiles of 4 output rows
    int co   = (blockIdx.x >> 3) & 31;
    int b    = blockIdx.x >> 8;
    int r0   = tile * 4;

    // ---- stage x tile as vertical-pair half2: 16 ci x 5 rr x 8 col-groups = 640
    #pragma unroll
    for (int i = 0; i < 5; i++) {
        int idx = tid + i * 128;
        int c4  = idx & 7;
        int rr  = (idx >> 3) % 5;
        int ci  = idx / 40;
        int g0  = r0 - 1 + rr;            // low-half tap row
        int g1  = r0 + rr;                // high-half tap row
        const float* base = x + ((b * NCI + ci) * HH) * WW + c4 * 4;
        float4 v0 = make_float4(0.f, 0.f, 0.f, 0.f);
        float4 v1 = make_float4(0.f, 0.f, 0.f, 0.f);
        if ((unsigned)g0 < 32u) v0 = *(const float4*)(base + g0 * WW);
        if ((unsigned)g1 < 32u) v1 = *(const float4*)(base + g1 * WW);
        int cb0 = c4 * 4 + 1;
        sxp[ci][rr][cb0 + 0] = __floats2half2_rn(v0.x, v1.x);
        sxp[ci][rr][cb0 + 1] = __floats2half2_rn(v0.y, v1.y);
        sxp[ci][rr][cb0 + 2] = __floats2half2_rn(v0.z, v1.z);
        sxp[ci][rr][cb0 + 3] = __floats2half2_rn(v0.w, v1.w);
    }
    if (tid < 80) {                       // zero pad columns: 16 ci x 5 rr
        int ci = tid / 5, rr = tid % 5;
        sxp[ci][rr][0]  = __float2half2_rn(0.f);
        sxp[ci][rr][33] = __float2half2_rn(0.f);
    }

    // ---- pack params for this co (432 terms = 108 float4 groups)
    float cb = 0.0f;
    if (tid < NTERM / 4) {
        const float4* k4 = (const float4*)(k    + co * NTERM);
        const float4* e4 = (const float4*)(Ec   + co * NTERM);
        const float4* p4 = (const float4*)(Ps   + co * NTERM);
        const float4* b4 = (const float4*)(bias + co * NTERM);
        const float4* c4 = (const float4*)(coef + co * NTERM);
        float4 kk = k4[tid], ee = e4[tid], pp = p4[tid], bb = b4[tid], cc = c4[tid];
        float kkv[4] = {kk.x, kk.y, kk.z, kk.w};
        float eev[4] = {ee.x, ee.y, ee.z, ee.w};
        float ppv[4] = {pp.x, pp.y, pp.z, pp.w};
        float bbv[4] = {bb.x, bb.y, bb.z, bb.w};
        float ccv[4] = {cc.x, cc.y, cc.z, cc.w};
        #pragma unroll
        for (int j = 0; j < 4; j++) {
            float ke = kkv[j] * eev[j];
            __half2 e5 = __float2half2_rn(5.0f * eev[j]);
            __half2 kh = __float2half2_rn(kkv[j]);
            __half2 z9 = __float2half2_rn(0.9f * ke);
            __half2 w1 = __float2half2_rn(0.1f * ke);
            uint4 u;
            u.x = *(unsigned*)&e5;
            u.y = *(unsigned*)&kh;
            u.z = *(unsigned*)&z9;
            u.w = *(unsigned*)&w1;
            sA[tid * 4 + j] = u;
            sC2[tid * 4 + j] = __float2half2_rn(ccv[j] * ppv[j]);
            cb += ccv[j] * bbv[j];
        }
    }
    // block-reduce cb (position-independent term)
    #pragma unroll
    for (int s = 16; s > 0; s >>= 1)
        cb += __shfl_xor_sync(0xFFFFFFFFu, cb, s);
    if ((tid & 31) == 0) sRed[tid >> 5] = cb;
    __syncthreads();
    float bc = (sRed[0] + sRed[1]) + (sRed[2] + sRed[3]) + out_bias[co];

    int cig = tid >> 5;       // ci-group: 0..3 (4 channels each)
    int wo  = tid & 31;       // output col

    const __half2 FIVE2 = __float2half2_rn(5.0f);
    const __half2 ZERO2 = __float2half2_rn(0.0f);

    float acc0 = 0.f, acc1 = 0.f, acc2 = 0.f, acc3 = 0.f;

    #pragma unroll 1
    for (int c4i = 0; c4i < 4; c4i++) {
        int ci = cig * 4 + c4i;
        // 5 sliding row-pairs x 3 cols cover all taps of all 4 pixels:
        //  pair A (pixels r0, r0+1):   xh[dy*3+dx]
        //  pair B (pixels r0+2, r0+3): xh[(dy+2)*3+dx]
        __half2 xh[15];
        #pragma unroll
        for (int rr = 0; rr < 5; rr++)
            #pragma unroll
            for (int dx = 0; dx < 3; dx++)
                xh[rr * 3 + dx] = sxp[ci][rr][wo + dx];

        const uint4*   pa = &sA[ci * 27];
        const __half2* pc = &sC2[ci * 27];
        #pragma unroll
        for (int q0 = 0; q0 < 27; q0 += 3) {  // windows of 3 terms
            __half2 wA = ZERO2, wB = ZERO2;
            #pragma unroll
            for (int j = 0; j < 3; j++) {
                int q = q0 + j;               // q = nb*9 + dy*3 + dx
                uint4   u   = pa[q];
                __half2 cp2 = pc[q];
                __half2 e5 = *(__half2*)&u.x;
                __half2 kh = *(__half2*)&u.y;
                __half2 z9 = *(__half2*)&u.z;
                __half2 w1 = *(__half2*)&u.w;
                int ij = q % 9;
                int dy = ij / 3, dxx = ij % 3;
                __half2 xA = xh[dy * 3 + dxx];
                __half2 xB = xh[(dy + 2) * 3 + dxx];
                __half2 yA = __hfma2(xA, FIVE2, e5);
                __half2 yB = __hfma2(xB, FIVE2, e5);
                __half2 gA = __hfma2(xA, kh, z9);
                __half2 gB = __hfma2(xB, kh, z9);
                __half2 t1A, t1B;
                if (q < 11) {                 // f = 11/27: FMA-pipe polynomial
                    t1A = tanh2_poly(yA);
                    t1B = tanh2_poly(yB);
                } else {                      // MUFU
                    t1A = tanh2_approx(yA);
                    t1B = tanh2_approx(yB);
                }
                __half2 t2A = tanh2_approx(__hfma2(t1A, w1, gA));
                __half2 t2B = tanh2_approx(__hfma2(t1B, w1, gB));
                wA = __hfma2(cp2, t2A, wA);   // f16 window accumulate
                wB = __hfma2(cp2, t2B, wB);
            }
            // flush window to f32 accumulators
            float2 fA = __half22float2(wA);
            float2 fB = __half22float2(wB);
            acc0 += fA.x;
            acc1 += fA.y;
            acc2 += fB.x;
            acc3 += fB.y;
        }
    }

    if (cig > 0) {
        sP[cig - 1][wo][0] = acc0;
        sP[cig - 1][wo][1] = acc1;
        sP[cig - 1][wo][2] = acc2;
        sP[cig - 1][wo][3] = acc3;
    }
    __syncthreads();
    if (cig == 0) {
        float r[4] = {acc0, acc1, acc2, acc3};
        #pragma unroll
        for (int j = 0; j < 4; j++) {
            float v = ((r[j] + sP[0][wo][j]) + (sP[1][wo][j] + sP[2][wo][j])) + bc;
            out[(((b * NCO + co) * HH + (r0 + j)) * WW) + wo] = v;
        }
    }
}

extern "C" void kernel_launch(void* const* d_in, const int* in_sizes, int n_in,
                              void* d_out, int out_size) {
    const float* x        = (const float*)d_in[0];
    const float* k        = (const float*)d_in[1];
    const float* Ec       = (const float*)d_in[2];
    const float* Ps       = (const float*)d_in[3];
    const float* bias     = (const float*)d_in[4];
    const float* coef     = (const float*)d_in[5];
    const float* out_bias = (const float*)d_in[6];
    float* out = (float*)d_out;

    ferro_main_kernel<<<NBATCH * NCO * 8, 128>>>(x, k, Ec, Ps, bias, coef, out_bias, out);
}